// round 2
// baseline (speedup 1.0000x reference)
#include <cuda_runtime.h>
#include <cuda_bf16.h>

#define N_NODES 50000
#define N_EDGES 1600000
#define IN_FEAT 256
#define HIDDEN  128
#define N_CLASSES 16

// ---------------- scratch (device globals; no allocation allowed) ----------------
__device__ int   g_is64;
__device__ int   g_cnt[N_NODES];
__device__ int   g_row_ptr[N_NODES + 1];
__device__ int   g_cursor[N_NODES];
__device__ int   g_col[N_EDGES];
__device__ float g_dis[N_NODES];
__device__ __align__(16) float g_hs[N_NODES * HIDDEN];     // (X@W1) * dis[row]
__device__ __align__(16) float g_a1[N_NODES * HIDDEN];     // relu(agg1 + b1)
__device__ __align__(16) float g_hs2[N_NODES * N_CLASSES]; // (a1@W2) * dis[row]

// ---------------- edge index dtype probe ----------------
// If edge_index is int64 (values < 50000 >= 0), every odd 32-bit word is 0.
// For random int32 values in [0,50000), 128 consecutive odd words all being
// zero has probability ~ (1/50000)^128 ~= 0.
__global__ void k_detect(const int* __restrict__ ei) {
    int is64 = 1;
    for (int i = 1; i < 256; i += 2)
        if (ei[i] != 0) { is64 = 0; break; }
    g_is64 = is64;
}

__device__ __forceinline__ int load_idx(const void* ei, long long pos) {
    if (g_is64) return (int)((const long long*)ei)[pos];
    return ((const int*)ei)[pos];
}

// ---------------- CSR build ----------------
__global__ void k_zero_cnt() {
    int i = blockIdx.x * blockDim.x + threadIdx.x;
    if (i < N_NODES) g_cnt[i] = 0;
}

__global__ void k_count(const void* __restrict__ ei) {
    int e = blockIdx.x * blockDim.x + threadIdx.x;
    if (e < N_EDGES) {
        int d = load_idx(ei, (long long)N_EDGES + e);
        if ((unsigned)d < N_NODES) atomicAdd(&g_cnt[d], 1);
    }
}

// single-block exclusive scan over 50000 counts; also computes dis = rsqrt(deg+1)
__global__ void k_scan() {
    const int T = 1024;
    const int ITEMS = (N_NODES + T - 1) / T; // 49
    __shared__ int sums[T];
    int t = threadIdx.x;
    int base = t * ITEMS;
    int local = 0;
    for (int i = 0; i < ITEMS; i++) {
        int idx = base + i;
        if (idx < N_NODES) local += g_cnt[idx];
    }
    sums[t] = local;
    __syncthreads();
    // Hillis-Steele inclusive scan
    for (int off = 1; off < T; off <<= 1) {
        int v = (t >= off) ? sums[t - off] : 0;
        __syncthreads();
        sums[t] += v;
        __syncthreads();
    }
    int run = (t == 0) ? 0 : sums[t - 1];
    for (int i = 0; i < ITEMS; i++) {
        int idx = base + i;
        if (idx < N_NODES) {
            g_row_ptr[idx] = run;
            g_cursor[idx]  = run;
            int c = g_cnt[idx];
            g_dis[idx] = rsqrtf((float)(c + 1));
            run += c;
        }
    }
    if (t == T - 1) g_row_ptr[N_NODES] = sums[T - 1];
}

__global__ void k_scatter(const void* __restrict__ ei) {
    int e = blockIdx.x * blockDim.x + threadIdx.x;
    if (e < N_EDGES) {
        int s = load_idx(ei, e);
        int d = load_idx(ei, (long long)N_EDGES + e);
        if ((unsigned)d < N_NODES && (unsigned)s < N_NODES) {
            int p = atomicAdd(&g_cursor[d], 1);
            g_col[p] = s;
        }
    }
}

// ---------------- GEMM1: hs = (X @ W1) * dis[row]   [50000x256]x[256x128] ----------------
// BM=64, BN=128, BK=32, 256 threads, each computes 4x8.
__global__ __launch_bounds__(256) void k_gemm1(const float* __restrict__ X,
                                               const float* __restrict__ W) {
    __shared__ float As[32][65];   // [k][m], padded
    __shared__ float Bs[32][128];  // [k][n]
    const int rowBase = blockIdx.x * 64;
    const int tid = threadIdx.x;
    const int ty = tid / 16;   // 0..15 -> rows ty*4..
    const int tx = tid % 16;   // 0..15 -> cols tx*8..

    float acc[4][8];
#pragma unroll
    for (int m = 0; m < 4; m++)
#pragma unroll
        for (int n = 0; n < 8; n++) acc[m][n] = 0.f;

    for (int k0 = 0; k0 < IN_FEAT; k0 += 32) {
        // load A tile 64x32 (512 float4), transposed into As[k][m]
#pragma unroll
        for (int i = 0; i < 2; i++) {
            int idx = tid + i * 256;
            int r = idx >> 3;          // 0..63
            int c4 = idx & 7;          // 0..7
            int grow = rowBase + r;
            float4 v = make_float4(0.f, 0.f, 0.f, 0.f);
            if (grow < N_NODES)
                v = *reinterpret_cast<const float4*>(&X[(size_t)grow * IN_FEAT + k0 + c4 * 4]);
            int kk = c4 * 4;
            As[kk + 0][r] = v.x;
            As[kk + 1][r] = v.y;
            As[kk + 2][r] = v.z;
            As[kk + 3][r] = v.w;
        }
        // load B tile 32x128 (1024 float4)
#pragma unroll
        for (int i = 0; i < 4; i++) {
            int idx = tid + i * 256;
            int r = idx >> 5;          // 0..31
            int c4 = idx & 31;         // 0..31
            *reinterpret_cast<float4*>(&Bs[r][c4 * 4]) =
                *reinterpret_cast<const float4*>(&W[(size_t)(k0 + r) * HIDDEN + c4 * 4]);
        }
        __syncthreads();

#pragma unroll
        for (int k = 0; k < 32; k++) {
            float a0 = As[k][ty * 4 + 0];
            float a1 = As[k][ty * 4 + 1];
            float a2 = As[k][ty * 4 + 2];
            float a3 = As[k][ty * 4 + 3];
            float4 b0 = *reinterpret_cast<const float4*>(&Bs[k][tx * 8]);
            float4 b1 = *reinterpret_cast<const float4*>(&Bs[k][tx * 8 + 4]);
            float bb[8] = {b0.x, b0.y, b0.z, b0.w, b1.x, b1.y, b1.z, b1.w};
            float aa[4] = {a0, a1, a2, a3};
#pragma unroll
            for (int m = 0; m < 4; m++)
#pragma unroll
                for (int n = 0; n < 8; n++) acc[m][n] = fmaf(aa[m], bb[n], acc[m][n]);
        }
        __syncthreads();
    }

#pragma unroll
    for (int m = 0; m < 4; m++) {
        int row = rowBase + ty * 4 + m;
        if (row < N_NODES) {
            float d = g_dis[row];
            float4 o0, o1;
            o0.x = acc[m][0] * d; o0.y = acc[m][1] * d; o0.z = acc[m][2] * d; o0.w = acc[m][3] * d;
            o1.x = acc[m][4] * d; o1.y = acc[m][5] * d; o1.z = acc[m][6] * d; o1.w = acc[m][7] * d;
            *reinterpret_cast<float4*>(&g_hs[(size_t)row * HIDDEN + tx * 8])     = o0;
            *reinterpret_cast<float4*>(&g_hs[(size_t)row * HIDDEN + tx * 8 + 4]) = o1;
        }
    }
}

// ---------------- Aggregation layer 1: a1 = relu(dis[d]*(sum hs[s] + hs[d]) + b1) ----------------
// one warp per node; lane covers 4 floats (float4) of the 128-wide row
__global__ __launch_bounds__(256) void k_agg1(const float* __restrict__ b1) {
    int w = (blockIdx.x * blockDim.x + threadIdx.x) >> 5;
    if (w >= N_NODES) return;
    int lane = threadIdx.x & 31;
    const float4* hs4 = reinterpret_cast<const float4*>(g_hs);

    float4 acc = hs4[(size_t)w * 32 + lane];  // self loop term (hs = h*dis)
    int s = g_row_ptr[w];
    int e = g_row_ptr[w + 1];
    for (int i = s; i < e; i++) {
        int src = g_col[i];
        float4 v = hs4[(size_t)src * 32 + lane];
        acc.x += v.x; acc.y += v.y; acc.z += v.z; acc.w += v.w;
    }
    float d = g_dis[w];
    float4 b = reinterpret_cast<const float4*>(b1)[lane];
    float4 r;
    r.x = fmaxf(fmaf(d, acc.x, b.x), 0.f);
    r.y = fmaxf(fmaf(d, acc.y, b.y), 0.f);
    r.z = fmaxf(fmaf(d, acc.z, b.z), 0.f);
    r.w = fmaxf(fmaf(d, acc.w, b.w), 0.f);
    reinterpret_cast<float4*>(g_a1)[(size_t)w * 32 + lane] = r;
}

// ---------------- GEMM2: hs2 = (a1 @ W2) * dis[row]   [50000x128]x[128x16] ----------------
__global__ __launch_bounds__(256) void k_gemm2(const float* __restrict__ W2) {
    __shared__ float Ws[HIDDEN * N_CLASSES]; // 2048 floats
    int tid = threadIdx.x;
    for (int i = tid; i < HIDDEN * N_CLASSES; i += 256) Ws[i] = W2[i];
    __syncthreads();
    int idx = blockIdx.x * 256 + tid;
    if (idx >= N_NODES * N_CLASSES) return;
    int n = idx >> 4;
    int c = idx & 15;
    const float* row = &g_a1[(size_t)n * HIDDEN];
    float acc = 0.f;
#pragma unroll
    for (int k = 0; k < HIDDEN; k++) acc = fmaf(row[k], Ws[k * N_CLASSES + c], acc);
    g_hs2[idx] = acc * g_dis[n];
}

// ---------------- Aggregation layer 2 + bias + softmax ----------------
// 2 nodes per warp, 16 lanes per node
__global__ __launch_bounds__(256) void k_agg2(const float* __restrict__ b2,
                                              float* __restrict__ out) {
    int w = (blockIdx.x * blockDim.x + threadIdx.x) >> 5;
    int lane = threadIdx.x & 31;
    int n = w * 2 + (lane >> 4);
    int c = lane & 15;
    if (n >= N_NODES) return;

    float acc = g_hs2[(size_t)n * N_CLASSES + c];  // self loop term
    int s = g_row_ptr[n];
    int e = g_row_ptr[n + 1];
    for (int i = s; i < e; i++) {
        int src = g_col[i];
        acc += g_hs2[(size_t)src * N_CLASSES + c];
    }
    float logit = fmaf(g_dis[n], acc, b2[c]);
    out[(size_t)n * N_CLASSES + c] = logit;

    // softmax over 16 lanes (width-16 butterflies)
    float m = logit;
#pragma unroll
    for (int o = 8; o > 0; o >>= 1) m = fmaxf(m, __shfl_xor_sync(0xffffffffu, m, o, 16));
    float ex = expf(logit - m);
    float sum = ex;
#pragma unroll
    for (int o = 8; o > 0; o >>= 1) sum += __shfl_xor_sync(0xffffffffu, sum, o, 16);
    out[(size_t)N_NODES * N_CLASSES + (size_t)n * N_CLASSES + c] = ex / sum;
}

// ---------------- launch ----------------
extern "C" void kernel_launch(void* const* d_in, const int* in_sizes, int n_in,
                              void* d_out, int out_size) {
    const float* X  = (const float*)d_in[0];
    const void*  EI = d_in[1];
    const float* W1 = (const float*)d_in[2];
    const float* B1 = (const float*)d_in[3];
    const float* W2 = (const float*)d_in[4];
    const float* B2 = (const float*)d_in[5];
    float* out = (float*)d_out;

    // detect edge_index dtype (int32 vs int64)
    k_detect<<<1, 1>>>((const int*)EI);

    // CSR build
    k_zero_cnt<<<(N_NODES + 255) / 256, 256>>>();
    k_count<<<(N_EDGES + 255) / 256, 256>>>(EI);
    k_scan<<<1, 1024>>>();
    k_scatter<<<(N_EDGES + 255) / 256, 256>>>(EI);

    // layer 1
    k_gemm1<<<(N_NODES + 63) / 64, 256>>>(X, W1);
    k_agg1<<<(N_NODES * 32 + 255) / 256, 256>>>(B1);

    // layer 2
    k_gemm2<<<(N_NODES * N_CLASSES + 255) / 256, 256>>>(W2);
    k_agg2<<<(N_NODES * 16 + 255) / 256, 256>>>(B2, out);
}

// round 3
// speedup vs baseline: 1.3415x; 1.3415x over previous
#include <cuda_runtime.h>
#include <cuda_bf16.h>

#define N_NODES 50000
#define N_EDGES 1600000
#define IN_FEAT 256
#define HIDDEN  128
#define N_CLASSES 16

#define SCAN_CHUNK 256
#define N_SCAN_BLOCKS ((N_NODES + SCAN_CHUNK - 1) / SCAN_CHUNK)   // 196

// ---------------- scratch (device globals; no allocation allowed) ----------------
__device__ int   g_is64;
__device__ int   g_cnt[N_NODES];
__device__ int   g_row_ptr[N_NODES + 1];
__device__ int   g_cursor[N_NODES];
__device__ int   g_col[N_EDGES];
__device__ int   g_block_sums[N_SCAN_BLOCKS];
__device__ int   g_block_off[N_SCAN_BLOCKS];   // inclusive scan of block sums
__device__ float g_dis[N_NODES];
__device__ __align__(16) float g_hs[N_NODES * HIDDEN];     // (X@W1) * dis[row]
__device__ __align__(16) float g_a1[N_NODES * HIDDEN];     // relu(agg1 + b1)
__device__ __align__(16) float g_hs2[N_NODES * N_CLASSES]; // (a1@W2) * dis[row]

// ---------------- edge index dtype probe ----------------
__global__ void k_detect(const int* __restrict__ ei) {
    int is64 = 1;
    for (int i = 1; i < 256; i += 2)
        if (ei[i] != 0) { is64 = 0; break; }
    g_is64 = is64;
}

__device__ __forceinline__ int load_idx(const void* ei, long long pos) {
    if (g_is64) return (int)((const long long*)ei)[pos];
    return ((const int*)ei)[pos];
}

// ---------------- CSR build ----------------
__global__ void k_zero_cnt() {
    int i = blockIdx.x * blockDim.x + threadIdx.x;
    if (i < N_NODES) g_cnt[i] = 0;
}

__global__ void k_count(const void* __restrict__ ei) {
    int e = blockIdx.x * blockDim.x + threadIdx.x;
    if (e < N_EDGES) {
        int d = load_idx(ei, (long long)N_EDGES + e);
        if ((unsigned)d < N_NODES) atomicAdd(&g_cnt[d], 1);
    }
}

// pass 1: per-block reduction of counts (coalesced)
__global__ __launch_bounds__(SCAN_CHUNK) void k_blocksum() {
    __shared__ int red[SCAN_CHUNK / 32];
    int idx = blockIdx.x * SCAN_CHUNK + threadIdx.x;
    int v = (idx < N_NODES) ? g_cnt[idx] : 0;
#pragma unroll
    for (int o = 16; o > 0; o >>= 1) v += __shfl_down_sync(0xffffffffu, v, o);
    int lane = threadIdx.x & 31, w = threadIdx.x >> 5;
    if (lane == 0) red[w] = v;
    __syncthreads();
    if (threadIdx.x == 0) {
        int s = 0;
#pragma unroll
        for (int i = 0; i < SCAN_CHUNK / 32; i++) s += red[i];
        g_block_sums[blockIdx.x] = s;
    }
}

// pass 2: single small block scans 196 block sums (inclusive)
__global__ __launch_bounds__(256) void k_scan_bs() {
    __shared__ int s[256];
    int t = threadIdx.x;
    s[t] = (t < N_SCAN_BLOCKS) ? g_block_sums[t] : 0;
    __syncthreads();
#pragma unroll
    for (int off = 1; off < 256; off <<= 1) {
        int v = (t >= off) ? s[t - off] : 0;
        __syncthreads();
        s[t] += v;
        __syncthreads();
    }
    if (t < N_SCAN_BLOCKS) g_block_off[t] = s[t];
    if (t == 255) g_row_ptr[N_NODES] = s[255];  // total (incl. padded zeros)
}

// pass 3: per-block exclusive scan + offset; write row_ptr/cursor/dis
__global__ __launch_bounds__(SCAN_CHUNK) void k_scan_final() {
    __shared__ int s[SCAN_CHUNK];
    int t = threadIdx.x;
    int idx = blockIdx.x * SCAN_CHUNK + t;
    int c = (idx < N_NODES) ? g_cnt[idx] : 0;
    s[t] = c;
    __syncthreads();
#pragma unroll
    for (int off = 1; off < SCAN_CHUNK; off <<= 1) {
        int v = (t >= off) ? s[t - off] : 0;
        __syncthreads();
        s[t] += v;
        __syncthreads();
    }
    int blockBase = (blockIdx.x == 0) ? 0 : g_block_off[blockIdx.x - 1];
    if (idx < N_NODES) {
        int excl = blockBase + s[t] - c;   // exclusive prefix
        g_row_ptr[idx] = excl;
        g_cursor[idx]  = excl;
        g_dis[idx] = rsqrtf((float)(c + 1));
    }
}

__global__ void k_scatter(const void* __restrict__ ei) {
    int e = blockIdx.x * blockDim.x + threadIdx.x;
    if (e < N_EDGES) {
        int s = load_idx(ei, e);
        int d = load_idx(ei, (long long)N_EDGES + e);
        if ((unsigned)d < N_NODES && (unsigned)s < N_NODES) {
            int p = atomicAdd(&g_cursor[d], 1);
            g_col[p] = s;
        }
    }
}

// ---------------- GEMM1: hs = (X @ W1) * dis[row]   [50000x256]x[256x128] ----------------
// BM=64, BN=128, BK=32, 256 threads, each computes 4x8.
__global__ __launch_bounds__(256) void k_gemm1(const float* __restrict__ X,
                                               const float* __restrict__ W) {
    __shared__ float As[32][65];   // [k][m], padded
    __shared__ float Bs[32][128];  // [k][n]
    const int rowBase = blockIdx.x * 64;
    const int tid = threadIdx.x;
    const int ty = tid / 16;   // 0..15 -> rows ty*4..
    const int tx = tid % 16;   // 0..15 -> cols tx*8..

    float acc[4][8];
#pragma unroll
    for (int m = 0; m < 4; m++)
#pragma unroll
        for (int n = 0; n < 8; n++) acc[m][n] = 0.f;

    for (int k0 = 0; k0 < IN_FEAT; k0 += 32) {
#pragma unroll
        for (int i = 0; i < 2; i++) {
            int idx = tid + i * 256;
            int r = idx >> 3;
            int c4 = idx & 7;
            int grow = rowBase + r;
            float4 v = make_float4(0.f, 0.f, 0.f, 0.f);
            if (grow < N_NODES)
                v = *reinterpret_cast<const float4*>(&X[(size_t)grow * IN_FEAT + k0 + c4 * 4]);
            int kk = c4 * 4;
            As[kk + 0][r] = v.x;
            As[kk + 1][r] = v.y;
            As[kk + 2][r] = v.z;
            As[kk + 3][r] = v.w;
        }
#pragma unroll
        for (int i = 0; i < 4; i++) {
            int idx = tid + i * 256;
            int r = idx >> 5;
            int c4 = idx & 31;
            *reinterpret_cast<float4*>(&Bs[r][c4 * 4]) =
                *reinterpret_cast<const float4*>(&W[(size_t)(k0 + r) * HIDDEN + c4 * 4]);
        }
        __syncthreads();

#pragma unroll
        for (int k = 0; k < 32; k++) {
            float a0 = As[k][ty * 4 + 0];
            float a1 = As[k][ty * 4 + 1];
            float a2 = As[k][ty * 4 + 2];
            float a3 = As[k][ty * 4 + 3];
            float4 b0 = *reinterpret_cast<const float4*>(&Bs[k][tx * 8]);
            float4 b1 = *reinterpret_cast<const float4*>(&Bs[k][tx * 8 + 4]);
            float bb[8] = {b0.x, b0.y, b0.z, b0.w, b1.x, b1.y, b1.z, b1.w};
            float aa[4] = {a0, a1, a2, a3};
#pragma unroll
            for (int m = 0; m < 4; m++)
#pragma unroll
                for (int n = 0; n < 8; n++) acc[m][n] = fmaf(aa[m], bb[n], acc[m][n]);
        }
        __syncthreads();
    }

#pragma unroll
    for (int m = 0; m < 4; m++) {
        int row = rowBase + ty * 4 + m;
        if (row < N_NODES) {
            float d = g_dis[row];
            float4 o0, o1;
            o0.x = acc[m][0] * d; o0.y = acc[m][1] * d; o0.z = acc[m][2] * d; o0.w = acc[m][3] * d;
            o1.x = acc[m][4] * d; o1.y = acc[m][5] * d; o1.z = acc[m][6] * d; o1.w = acc[m][7] * d;
            *reinterpret_cast<float4*>(&g_hs[(size_t)row * HIDDEN + tx * 8])     = o0;
            *reinterpret_cast<float4*>(&g_hs[(size_t)row * HIDDEN + tx * 8 + 4]) = o1;
        }
    }
}

// ---------------- Aggregation layer 1: a1 = relu(dis[d]*(sum hs[s] + hs[d]) + b1) ----------------
__global__ __launch_bounds__(256) void k_agg1(const float* __restrict__ b1) {
    int w = (blockIdx.x * blockDim.x + threadIdx.x) >> 5;
    if (w >= N_NODES) return;
    int lane = threadIdx.x & 31;
    const float4* hs4 = reinterpret_cast<const float4*>(g_hs);

    float4 acc = hs4[(size_t)w * 32 + lane];  // self loop term (hs = h*dis)
    int s = g_row_ptr[w];
    int e = g_row_ptr[w + 1];
    for (int i = s; i < e; i++) {
        int src = g_col[i];
        float4 v = hs4[(size_t)src * 32 + lane];
        acc.x += v.x; acc.y += v.y; acc.z += v.z; acc.w += v.w;
    }
    float d = g_dis[w];
    float4 b = reinterpret_cast<const float4*>(b1)[lane];
    float4 r;
    r.x = fmaxf(fmaf(d, acc.x, b.x), 0.f);
    r.y = fmaxf(fmaf(d, acc.y, b.y), 0.f);
    r.z = fmaxf(fmaf(d, acc.z, b.z), 0.f);
    r.w = fmaxf(fmaf(d, acc.w, b.w), 0.f);
    reinterpret_cast<float4*>(g_a1)[(size_t)w * 32 + lane] = r;
}

// ---------------- GEMM2: hs2 = (a1 @ W2) * dis[row]   [50000x128]x[128x16] ----------------
__global__ __launch_bounds__(256) void k_gemm2(const float* __restrict__ W2) {
    __shared__ float Ws[HIDDEN * N_CLASSES]; // 2048 floats
    int tid = threadIdx.x;
    for (int i = tid; i < HIDDEN * N_CLASSES; i += 256) Ws[i] = W2[i];
    __syncthreads();
    int idx = blockIdx.x * 256 + tid;
    if (idx >= N_NODES * N_CLASSES) return;
    int n = idx >> 4;
    int c = idx & 15;
    const float* row = &g_a1[(size_t)n * HIDDEN];
    float acc = 0.f;
#pragma unroll
    for (int k = 0; k < HIDDEN; k++) acc = fmaf(row[k], Ws[k * N_CLASSES + c], acc);
    g_hs2[idx] = acc * g_dis[n];
}

// ---------------- Aggregation layer 2 + bias + softmax ----------------
__global__ __launch_bounds__(256) void k_agg2(const float* __restrict__ b2,
                                              float* __restrict__ out) {
    int w = (blockIdx.x * blockDim.x + threadIdx.x) >> 5;
    int lane = threadIdx.x & 31;
    int n = w * 2 + (lane >> 4);
    int c = lane & 15;
    if (n >= N_NODES) return;

    float acc = g_hs2[(size_t)n * N_CLASSES + c];  // self loop term
    int s = g_row_ptr[n];
    int e = g_row_ptr[n + 1];
    for (int i = s; i < e; i++) {
        int src = g_col[i];
        acc += g_hs2[(size_t)src * N_CLASSES + c];
    }
    float logit = fmaf(g_dis[n], acc, b2[c]);
    out[(size_t)n * N_CLASSES + c] = logit;

    float m = logit;
#pragma unroll
    for (int o = 8; o > 0; o >>= 1) m = fmaxf(m, __shfl_xor_sync(0xffffffffu, m, o, 16));
    float ex = expf(logit - m);
    float sum = ex;
#pragma unroll
    for (int o = 8; o > 0; o >>= 1) sum += __shfl_xor_sync(0xffffffffu, sum, o, 16);
    out[(size_t)N_NODES * N_CLASSES + (size_t)n * N_CLASSES + c] = ex / sum;
}

// ---------------- launch ----------------
extern "C" void kernel_launch(void* const* d_in, const int* in_sizes, int n_in,
                              void* d_out, int out_size) {
    const float* X  = (const float*)d_in[0];
    const void*  EI = d_in[1];
    const float* W1 = (const float*)d_in[2];
    const float* B1 = (const float*)d_in[3];
    const float* W2 = (const float*)d_in[4];
    const float* B2 = (const float*)d_in[5];
    float* out = (float*)d_out;

    // detect edge_index dtype (int32 vs int64)
    k_detect<<<1, 1>>>((const int*)EI);

    // CSR build
    k_zero_cnt<<<(N_NODES + 255) / 256, 256>>>();
    k_count<<<(N_EDGES + 255) / 256, 256>>>(EI);
    k_blocksum<<<N_SCAN_BLOCKS, SCAN_CHUNK>>>();
    k_scan_bs<<<1, 256>>>();
    k_scan_final<<<N_SCAN_BLOCKS, SCAN_CHUNK>>>();
    k_scatter<<<(N_EDGES + 255) / 256, 256>>>(EI);

    // layer 1
    k_gemm1<<<(N_NODES + 63) / 64, 256>>>(X, W1);
    k_agg1<<<(N_NODES * 32 + 255) / 256, 256>>>(B1);

    // layer 2
    k_gemm2<<<(N_NODES * N_CLASSES + 255) / 256, 256>>>(W2);
    k_agg2<<<(N_NODES * 16 + 255) / 256, 256>>>(B2, out);
}

// round 4
// speedup vs baseline: 1.5092x; 1.1250x over previous
#include <cuda_runtime.h>
#include <cuda_bf16.h>

#define N_NODES 50000
#define N_EDGES 1600000
#define IN_FEAT 256
#define HIDDEN  128
#define N_CLASSES 16

#define SCAN_CHUNK 256
#define N_SCAN_BLOCKS ((N_NODES + SCAN_CHUNK - 1) / SCAN_CHUNK)   // 196

// ---------------- scratch (device globals; no allocation allowed) ----------------
__device__ int   g_is64;
__device__ int   g_cnt[N_NODES];
__device__ int   g_row_ptr[N_NODES + 1];
__device__ int   g_cursor[N_NODES];
__device__ int   g_col[N_EDGES];
__device__ int   g_block_sums[N_SCAN_BLOCKS];
__device__ int   g_block_off[N_SCAN_BLOCKS];
__device__ float g_dis[N_NODES];
__device__ __align__(16) float g_hs[N_NODES * HIDDEN];     // X@W1 (unscaled)
__device__ __align__(16) float g_a1[N_NODES * HIDDEN];     // relu(agg1 + b1)
__device__ __align__(16) float g_hs2[N_NODES * N_CLASSES]; // (a1@W2) * dis[row]

// ---------------- init: zero counts + edge dtype probe ----------------
__global__ void k_init(const int* __restrict__ ei) {
    int i = blockIdx.x * blockDim.x + threadIdx.x;
    if (i < N_NODES) g_cnt[i] = 0;
    if (i == 0) {
        int is64 = 1;
        for (int j = 1; j < 256; j += 2)
            if (ei[j] != 0) { is64 = 0; break; }
        g_is64 = is64;
    }
}

__device__ __forceinline__ int load_idx(const void* ei, long long pos) {
    if (g_is64) return (int)((const long long*)ei)[pos];
    return ((const int*)ei)[pos];
}

// ---------------- CSR build ----------------
__global__ void k_count(const void* __restrict__ ei) {
    int e = blockIdx.x * blockDim.x + threadIdx.x;
    if (e < N_EDGES) {
        int d = load_idx(ei, (long long)N_EDGES + e);
        if ((unsigned)d < N_NODES) atomicAdd(&g_cnt[d], 1);
    }
}

__global__ __launch_bounds__(SCAN_CHUNK) void k_blocksum() {
    __shared__ int red[SCAN_CHUNK / 32];
    int idx = blockIdx.x * SCAN_CHUNK + threadIdx.x;
    int v = (idx < N_NODES) ? g_cnt[idx] : 0;
#pragma unroll
    for (int o = 16; o > 0; o >>= 1) v += __shfl_down_sync(0xffffffffu, v, o);
    int lane = threadIdx.x & 31, w = threadIdx.x >> 5;
    if (lane == 0) red[w] = v;
    __syncthreads();
    if (threadIdx.x == 0) {
        int s = 0;
#pragma unroll
        for (int i = 0; i < SCAN_CHUNK / 32; i++) s += red[i];
        g_block_sums[blockIdx.x] = s;
    }
}

__global__ __launch_bounds__(256) void k_scan_bs() {
    __shared__ int s[256];
    int t = threadIdx.x;
    s[t] = (t < N_SCAN_BLOCKS) ? g_block_sums[t] : 0;
    __syncthreads();
#pragma unroll
    for (int off = 1; off < 256; off <<= 1) {
        int v = (t >= off) ? s[t - off] : 0;
        __syncthreads();
        s[t] += v;
        __syncthreads();
    }
    if (t < N_SCAN_BLOCKS) g_block_off[t] = s[t];
    if (t == 255) g_row_ptr[N_NODES] = s[255];
}

__global__ __launch_bounds__(SCAN_CHUNK) void k_scan_final() {
    __shared__ int s[SCAN_CHUNK];
    int t = threadIdx.x;
    int idx = blockIdx.x * SCAN_CHUNK + t;
    int c = (idx < N_NODES) ? g_cnt[idx] : 0;
    s[t] = c;
    __syncthreads();
#pragma unroll
    for (int off = 1; off < SCAN_CHUNK; off <<= 1) {
        int v = (t >= off) ? s[t - off] : 0;
        __syncthreads();
        s[t] += v;
        __syncthreads();
    }
    int blockBase = (blockIdx.x == 0) ? 0 : g_block_off[blockIdx.x - 1];
    if (idx < N_NODES) {
        int excl = blockBase + s[t] - c;
        g_row_ptr[idx] = excl;
        g_cursor[idx]  = excl;
        g_dis[idx] = rsqrtf((float)(c + 1));
    }
}

__global__ void k_scatter(const void* __restrict__ ei) {
    int e = blockIdx.x * blockDim.x + threadIdx.x;
    if (e < N_EDGES) {
        int s = load_idx(ei, e);
        int d = load_idx(ei, (long long)N_EDGES + e);
        if ((unsigned)d < N_NODES && (unsigned)s < N_NODES) {
            int p = atomicAdd(&g_cursor[d], 1);
            g_col[p] = s;
        }
    }
}

// ---------------- GEMM1: g_hs = X @ W1 (unscaled)  [50000x256]x[256x128] ----------------
// BM=128, BN=128, BK=16, 256 threads, 8x8 per thread, reg-prefetch double buffer.
#define BM 128
#define BN 128
#define BK 16

__global__ __launch_bounds__(256, 2) void k_gemm1(const float* __restrict__ X,
                                                  const float* __restrict__ W) {
    __shared__ float As[BK][BM + 4];   // transposed [k][m]
    __shared__ float Bs[BK][BN];       // [k][n]
    const int tid = threadIdx.x;
    const int rowBase = blockIdx.x * BM;
    const int tx = tid & 15;   // cols tx*8
    const int ty = tid >> 4;   // rows ty*8

    // A: 512 float4 (128 rows x 4 f4), 2 per thread
    const int ar0 = tid >> 2,        ac0 = tid & 3;
    const int ar1 = (tid + 256) >> 2, ac1 = (tid + 256) & 3;
    // B: 512 float4 (16 rows x 32 f4), 2 per thread
    const int br0 = tid >> 5,        bc0 = tid & 31;
    const int br1 = (tid + 256) >> 5, bc1 = (tid + 256) & 31;

    float4 aR0, aR1, bR0, bR1;

    auto loadG = [&](int k0) {
        aR0 = make_float4(0.f, 0.f, 0.f, 0.f);
        aR1 = make_float4(0.f, 0.f, 0.f, 0.f);
        if (rowBase + ar0 < N_NODES)
            aR0 = *reinterpret_cast<const float4*>(&X[(size_t)(rowBase + ar0) * IN_FEAT + k0 + ac0 * 4]);
        if (rowBase + ar1 < N_NODES)
            aR1 = *reinterpret_cast<const float4*>(&X[(size_t)(rowBase + ar1) * IN_FEAT + k0 + ac1 * 4]);
        bR0 = *reinterpret_cast<const float4*>(&W[(size_t)(k0 + br0) * HIDDEN + bc0 * 4]);
        bR1 = *reinterpret_cast<const float4*>(&W[(size_t)(k0 + br1) * HIDDEN + bc1 * 4]);
    };
    auto storeS = [&]() {
        int k = ac0 * 4;
        As[k + 0][ar0] = aR0.x; As[k + 1][ar0] = aR0.y; As[k + 2][ar0] = aR0.z; As[k + 3][ar0] = aR0.w;
        k = ac1 * 4;
        As[k + 0][ar1] = aR1.x; As[k + 1][ar1] = aR1.y; As[k + 2][ar1] = aR1.z; As[k + 3][ar1] = aR1.w;
        *reinterpret_cast<float4*>(&Bs[br0][bc0 * 4]) = bR0;
        *reinterpret_cast<float4*>(&Bs[br1][bc1 * 4]) = bR1;
    };

    float acc[8][8];
#pragma unroll
    for (int m = 0; m < 8; m++)
#pragma unroll
        for (int n = 0; n < 8; n++) acc[m][n] = 0.f;

    loadG(0);
    storeS();
    __syncthreads();

    const int NT = IN_FEAT / BK;  // 16
    for (int t = 0; t < NT; t++) {
        if (t + 1 < NT) loadG((t + 1) * BK);
#pragma unroll
        for (int k = 0; k < BK; k++) {
            float4 a0 = *reinterpret_cast<const float4*>(&As[k][ty * 8]);
            float4 a1 = *reinterpret_cast<const float4*>(&As[k][ty * 8 + 4]);
            float4 b0 = *reinterpret_cast<const float4*>(&Bs[k][tx * 8]);
            float4 b1 = *reinterpret_cast<const float4*>(&Bs[k][tx * 8 + 4]);
            float av[8] = {a0.x, a0.y, a0.z, a0.w, a1.x, a1.y, a1.z, a1.w};
            float bv[8] = {b0.x, b0.y, b0.z, b0.w, b1.x, b1.y, b1.z, b1.w};
#pragma unroll
            for (int m = 0; m < 8; m++)
#pragma unroll
                for (int n = 0; n < 8; n++) acc[m][n] = fmaf(av[m], bv[n], acc[m][n]);
        }
        if (t + 1 < NT) {
            __syncthreads();
            storeS();
            __syncthreads();
        }
    }

#pragma unroll
    for (int m = 0; m < 8; m++) {
        int row = rowBase + ty * 8 + m;
        if (row < N_NODES) {
            float4 o0 = make_float4(acc[m][0], acc[m][1], acc[m][2], acc[m][3]);
            float4 o1 = make_float4(acc[m][4], acc[m][5], acc[m][6], acc[m][7]);
            *reinterpret_cast<float4*>(&g_hs[(size_t)row * HIDDEN + tx * 8])     = o0;
            *reinterpret_cast<float4*>(&g_hs[(size_t)row * HIDDEN + tx * 8 + 4]) = o1;
        }
    }
}

// ---------------- Agg1: a1 = relu(dis[w]*(h[w]*dis[w] + sum h[s]*dis[s]) + b1) ----------------
__global__ __launch_bounds__(256) void k_agg1(const float* __restrict__ b1) {
    int w = (blockIdx.x * blockDim.x + threadIdx.x) >> 5;
    if (w >= N_NODES) return;
    int lane = threadIdx.x & 31;
    const float4* hs4 = reinterpret_cast<const float4*>(g_hs);

    float dw = g_dis[w];
    float4 self = hs4[(size_t)w * 32 + lane];
    float4 acc0, acc1, acc2, acc3;
    acc0.x = self.x * dw; acc0.y = self.y * dw; acc0.z = self.z * dw; acc0.w = self.w * dw;
    acc1 = make_float4(0.f, 0.f, 0.f, 0.f);
    acc2 = make_float4(0.f, 0.f, 0.f, 0.f);
    acc3 = make_float4(0.f, 0.f, 0.f, 0.f);

    int i = g_row_ptr[w];
    int e = g_row_ptr[w + 1];
    for (; i + 3 < e; i += 4) {
        int s0 = g_col[i], s1 = g_col[i + 1], s2 = g_col[i + 2], s3 = g_col[i + 3];
        float d0 = g_dis[s0], d1 = g_dis[s1], d2 = g_dis[s2], d3 = g_dis[s3];
        float4 v0 = hs4[(size_t)s0 * 32 + lane];
        float4 v1 = hs4[(size_t)s1 * 32 + lane];
        float4 v2 = hs4[(size_t)s2 * 32 + lane];
        float4 v3 = hs4[(size_t)s3 * 32 + lane];
        acc0.x = fmaf(v0.x, d0, acc0.x); acc0.y = fmaf(v0.y, d0, acc0.y);
        acc0.z = fmaf(v0.z, d0, acc0.z); acc0.w = fmaf(v0.w, d0, acc0.w);
        acc1.x = fmaf(v1.x, d1, acc1.x); acc1.y = fmaf(v1.y, d1, acc1.y);
        acc1.z = fmaf(v1.z, d1, acc1.z); acc1.w = fmaf(v1.w, d1, acc1.w);
        acc2.x = fmaf(v2.x, d2, acc2.x); acc2.y = fmaf(v2.y, d2, acc2.y);
        acc2.z = fmaf(v2.z, d2, acc2.z); acc2.w = fmaf(v2.w, d2, acc2.w);
        acc3.x = fmaf(v3.x, d3, acc3.x); acc3.y = fmaf(v3.y, d3, acc3.y);
        acc3.z = fmaf(v3.z, d3, acc3.z); acc3.w = fmaf(v3.w, d3, acc3.w);
    }
    for (; i < e; i++) {
        int s0 = g_col[i];
        float d0 = g_dis[s0];
        float4 v0 = hs4[(size_t)s0 * 32 + lane];
        acc0.x = fmaf(v0.x, d0, acc0.x); acc0.y = fmaf(v0.y, d0, acc0.y);
        acc0.z = fmaf(v0.z, d0, acc0.z); acc0.w = fmaf(v0.w, d0, acc0.w);
    }
    acc0.x += acc1.x + acc2.x + acc3.x;
    acc0.y += acc1.y + acc2.y + acc3.y;
    acc0.z += acc1.z + acc2.z + acc3.z;
    acc0.w += acc1.w + acc2.w + acc3.w;

    float4 b = reinterpret_cast<const float4*>(b1)[lane];
    float4 r;
    r.x = fmaxf(fmaf(dw, acc0.x, b.x), 0.f);
    r.y = fmaxf(fmaf(dw, acc0.y, b.y), 0.f);
    r.z = fmaxf(fmaf(dw, acc0.z, b.z), 0.f);
    r.w = fmaxf(fmaf(dw, acc0.w, b.w), 0.f);
    reinterpret_cast<float4*>(g_a1)[(size_t)w * 32 + lane] = r;
}

// ---------------- GEMM2: hs2 = (a1 @ W2) * dis[row]   [50000x128]x[128x16] ----------------
__global__ __launch_bounds__(256) void k_gemm2(const float* __restrict__ W2) {
    __shared__ float Ws[HIDDEN * N_CLASSES];
    int tid = threadIdx.x;
    for (int i = tid; i < HIDDEN * N_CLASSES; i += 256) Ws[i] = W2[i];
    __syncthreads();
    int idx = blockIdx.x * 256 + tid;
    if (idx >= N_NODES * N_CLASSES) return;
    int n = idx >> 4;
    int c = idx & 15;
    const float* row = &g_a1[(size_t)n * HIDDEN];
    float acc = 0.f;
#pragma unroll
    for (int k = 0; k < HIDDEN; k++) acc = fmaf(row[k], Ws[k * N_CLASSES + c], acc);
    g_hs2[idx] = acc * g_dis[n];
}

// ---------------- Agg2 + bias + softmax ----------------
__global__ __launch_bounds__(256) void k_agg2(const float* __restrict__ b2,
                                              float* __restrict__ out) {
    int w = (blockIdx.x * blockDim.x + threadIdx.x) >> 5;
    int lane = threadIdx.x & 31;
    int n = w * 2 + (lane >> 4);
    int c = lane & 15;
    if (n >= N_NODES) return;

    float acc0 = g_hs2[(size_t)n * N_CLASSES + c];  // self term
    float acc1 = 0.f, acc2 = 0.f, acc3 = 0.f;
    int i = g_row_ptr[n];
    int e = g_row_ptr[n + 1];
    for (; i + 3 < e; i += 4) {
        int s0 = g_col[i], s1 = g_col[i + 1], s2 = g_col[i + 2], s3 = g_col[i + 3];
        acc0 += g_hs2[(size_t)s0 * N_CLASSES + c];
        acc1 += g_hs2[(size_t)s1 * N_CLASSES + c];
        acc2 += g_hs2[(size_t)s2 * N_CLASSES + c];
        acc3 += g_hs2[(size_t)s3 * N_CLASSES + c];
    }
    for (; i < e; i++) acc0 += g_hs2[(size_t)g_col[i] * N_CLASSES + c];
    acc0 += acc1 + acc2 + acc3;

    float logit = fmaf(g_dis[n], acc0, b2[c]);
    out[(size_t)n * N_CLASSES + c] = logit;

    float m = logit;
#pragma unroll
    for (int o = 8; o > 0; o >>= 1) m = fmaxf(m, __shfl_xor_sync(0xffffffffu, m, o, 16));
    float ex = expf(logit - m);
    float sum = ex;
#pragma unroll
    for (int o = 8; o > 0; o >>= 1) sum += __shfl_xor_sync(0xffffffffu, sum, o, 16);
    out[(size_t)N_NODES * N_CLASSES + (size_t)n * N_CLASSES + c] = ex / sum;
}

// ---------------- launch ----------------
extern "C" void kernel_launch(void* const* d_in, const int* in_sizes, int n_in,
                              void* d_out, int out_size) {
    const float* X  = (const float*)d_in[0];
    const void*  EI = d_in[1];
    const float* W1 = (const float*)d_in[2];
    const float* B1 = (const float*)d_in[3];
    const float* W2 = (const float*)d_in[4];
    const float* B2 = (const float*)d_in[5];
    float* out = (float*)d_out;

    k_init<<<(N_NODES + 255) / 256, 256>>>((const int*)EI);           // 0
    k_count<<<(N_EDGES + 255) / 256, 256>>>(EI);                       // 1
    k_blocksum<<<N_SCAN_BLOCKS, SCAN_CHUNK>>>();                       // 2
    k_gemm1<<<(N_NODES + BM - 1) / BM, 256>>>(X, W1);                  // 3 (profiled)
    k_scan_bs<<<1, 256>>>();                                           // 4
    k_scan_final<<<N_SCAN_BLOCKS, SCAN_CHUNK>>>();                     // 5
    k_scatter<<<(N_EDGES + 255) / 256, 256>>>(EI);                     // 6
    k_agg1<<<(N_NODES * 32 + 255) / 256, 256>>>(B1);                   // 7
    k_gemm2<<<(N_NODES * N_CLASSES + 255) / 256, 256>>>(W2);           // 8
    k_agg2<<<(N_NODES * 16 + 255) / 256, 256>>>(B2, out);              // 9
}

// round 5
// speedup vs baseline: 1.5243x; 1.0100x over previous
#include <cuda_runtime.h>
#include <cuda_bf16.h>

#define N_NODES 50000
#define N_EDGES 1600000
#define IN_FEAT 256
#define HIDDEN  128
#define N_CLASSES 16

#define SCAN_CHUNK 256
#define N_SCAN_BLOCKS ((N_NODES + SCAN_CHUNK - 1) / SCAN_CHUNK)   // 196

// ---------------- scratch (device globals; no allocation allowed) ----------------
__device__ int   g_is64;
__device__ int   g_cnt[N_NODES];
__device__ int   g_row_ptr[N_NODES + 1];
__device__ int   g_cursor[N_NODES];
__device__ int   g_col[N_EDGES];
__device__ int   g_block_sums[N_SCAN_BLOCKS];
__device__ int   g_block_off[N_SCAN_BLOCKS];
__device__ float g_dis[N_NODES];
__device__ __align__(16) float g_hs[N_NODES * HIDDEN];     // X@W1 (unscaled)
__device__ __align__(16) float g_a1[N_NODES * HIDDEN];     // relu(agg1 + b1)
__device__ __align__(16) float g_hs2[N_NODES * N_CLASSES]; // (a1@W2) * dis[row]

// ---------------- init: zero counts + edge dtype probe ----------------
__global__ void k_init(const int* __restrict__ ei) {
    int i = blockIdx.x * blockDim.x + threadIdx.x;
    if (i < N_NODES) g_cnt[i] = 0;
    if (i == 0) {
        int is64 = 1;
        for (int j = 1; j < 256; j += 2)
            if (ei[j] != 0) { is64 = 0; break; }
        g_is64 = is64;
    }
}

__device__ __forceinline__ int load_idx(const void* ei, long long pos) {
    if (g_is64) return (int)((const long long*)ei)[pos];
    return ((const int*)ei)[pos];
}

// ---------------- CSR build ----------------
__global__ void k_count(const void* __restrict__ ei) {
    int e = blockIdx.x * blockDim.x + threadIdx.x;
    if (e < N_EDGES) {
        int d = load_idx(ei, (long long)N_EDGES + e);
        if ((unsigned)d < N_NODES) atomicAdd(&g_cnt[d], 1);
    }
}

__global__ __launch_bounds__(SCAN_CHUNK) void k_blocksum() {
    __shared__ int red[SCAN_CHUNK / 32];
    int idx = blockIdx.x * SCAN_CHUNK + threadIdx.x;
    int v = (idx < N_NODES) ? g_cnt[idx] : 0;
#pragma unroll
    for (int o = 16; o > 0; o >>= 1) v += __shfl_down_sync(0xffffffffu, v, o);
    int lane = threadIdx.x & 31, w = threadIdx.x >> 5;
    if (lane == 0) red[w] = v;
    __syncthreads();
    if (threadIdx.x == 0) {
        int s = 0;
#pragma unroll
        for (int i = 0; i < SCAN_CHUNK / 32; i++) s += red[i];
        g_block_sums[blockIdx.x] = s;
    }
}

__global__ __launch_bounds__(256) void k_scan_bs() {
    __shared__ int s[256];
    int t = threadIdx.x;
    s[t] = (t < N_SCAN_BLOCKS) ? g_block_sums[t] : 0;
    __syncthreads();
#pragma unroll
    for (int off = 1; off < 256; off <<= 1) {
        int v = (t >= off) ? s[t - off] : 0;
        __syncthreads();
        s[t] += v;
        __syncthreads();
    }
    if (t < N_SCAN_BLOCKS) g_block_off[t] = s[t];
    if (t == 255) g_row_ptr[N_NODES] = s[255];
}

__global__ __launch_bounds__(SCAN_CHUNK) void k_scan_final() {
    __shared__ int s[SCAN_CHUNK];
    int t = threadIdx.x;
    int idx = blockIdx.x * SCAN_CHUNK + t;
    int c = (idx < N_NODES) ? g_cnt[idx] : 0;
    s[t] = c;
    __syncthreads();
#pragma unroll
    for (int off = 1; off < SCAN_CHUNK; off <<= 1) {
        int v = (t >= off) ? s[t - off] : 0;
        __syncthreads();
        s[t] += v;
        __syncthreads();
    }
    int blockBase = (blockIdx.x == 0) ? 0 : g_block_off[blockIdx.x - 1];
    if (idx < N_NODES) {
        int excl = blockBase + s[t] - c;
        g_row_ptr[idx] = excl;
        g_cursor[idx]  = excl;
        g_dis[idx] = rsqrtf((float)(c + 1));
    }
}

__global__ void k_scatter(const void* __restrict__ ei) {
    int e = blockIdx.x * blockDim.x + threadIdx.x;
    if (e < N_EDGES) {
        int s = load_idx(ei, e);
        int d = load_idx(ei, (long long)N_EDGES + e);
        if ((unsigned)d < N_NODES && (unsigned)s < N_NODES) {
            int p = atomicAdd(&g_cursor[d], 1);
            g_col[p] = s;
        }
    }
}

// ---------------- GEMM1: g_hs = X @ W1 (unscaled)  [50000x256]x[256x128] ----------------
// BM=128, BN=128, BK=16, 256 threads, 8x8 per thread.
// TRUE double buffer: 2 smem stages, ONE __syncthreads per k-tile.
#define BM 128
#define BN 128
#define BK 16

__global__ __launch_bounds__(256, 2) void k_gemm1(const float* __restrict__ X,
                                                  const float* __restrict__ W) {
    __shared__ float As[2][BK][BM + 4];   // transposed [k][m]
    __shared__ float Bs[2][BK][BN];       // [k][n]
    const int tid = threadIdx.x;
    const int rowBase = blockIdx.x * BM;
    const int tx = tid & 15;   // cols tx*8
    const int ty = tid >> 4;   // rows ty*8

    // A: 512 float4 (128 rows x 4 f4), 2 per thread
    const int ar0 = tid >> 2,         ac0 = tid & 3;
    const int ar1 = (tid + 256) >> 2, ac1 = (tid + 256) & 3;
    // B: 512 float4 (16 rows x 32 f4), 2 per thread
    const int br0 = tid >> 5,         bc0 = tid & 31;
    const int br1 = (tid + 256) >> 5, bc1 = (tid + 256) & 31;

    const bool aok0 = (rowBase + ar0 < N_NODES);
    const bool aok1 = (rowBase + ar1 < N_NODES);

    float4 aR0, aR1, bR0, bR1;

    auto loadG = [&](int k0) {
        aR0 = make_float4(0.f, 0.f, 0.f, 0.f);
        aR1 = make_float4(0.f, 0.f, 0.f, 0.f);
        if (aok0)
            aR0 = *reinterpret_cast<const float4*>(&X[(size_t)(rowBase + ar0) * IN_FEAT + k0 + ac0 * 4]);
        if (aok1)
            aR1 = *reinterpret_cast<const float4*>(&X[(size_t)(rowBase + ar1) * IN_FEAT + k0 + ac1 * 4]);
        bR0 = *reinterpret_cast<const float4*>(&W[(size_t)(k0 + br0) * HIDDEN + bc0 * 4]);
        bR1 = *reinterpret_cast<const float4*>(&W[(size_t)(k0 + br1) * HIDDEN + bc1 * 4]);
    };
    auto storeS = [&](int buf) {
        int k = ac0 * 4;
        As[buf][k + 0][ar0] = aR0.x; As[buf][k + 1][ar0] = aR0.y;
        As[buf][k + 2][ar0] = aR0.z; As[buf][k + 3][ar0] = aR0.w;
        k = ac1 * 4;
        As[buf][k + 0][ar1] = aR1.x; As[buf][k + 1][ar1] = aR1.y;
        As[buf][k + 2][ar1] = aR1.z; As[buf][k + 3][ar1] = aR1.w;
        *reinterpret_cast<float4*>(&Bs[buf][br0][bc0 * 4]) = bR0;
        *reinterpret_cast<float4*>(&Bs[buf][br1][bc1 * 4]) = bR1;
    };

    float acc[8][8];
#pragma unroll
    for (int m = 0; m < 8; m++)
#pragma unroll
        for (int n = 0; n < 8; n++) acc[m][n] = 0.f;

    loadG(0);
    storeS(0);
    __syncthreads();

    const int NT = IN_FEAT / BK;  // 16
#pragma unroll 1
    for (int t = 0; t < NT; t++) {
        int cur = t & 1;
        if (t + 1 < NT) loadG((t + 1) * BK);   // global -> regs (overlaps compute)
#pragma unroll
        for (int k = 0; k < BK; k++) {
            float4 a0 = *reinterpret_cast<const float4*>(&As[cur][k][ty * 8]);
            float4 a1 = *reinterpret_cast<const float4*>(&As[cur][k][ty * 8 + 4]);
            float4 b0 = *reinterpret_cast<const float4*>(&Bs[cur][k][tx * 8]);
            float4 b1 = *reinterpret_cast<const float4*>(&Bs[cur][k][tx * 8 + 4]);
            float av[8] = {a0.x, a0.y, a0.z, a0.w, a1.x, a1.y, a1.z, a1.w};
            float bv[8] = {b0.x, b0.y, b0.z, b0.w, b1.x, b1.y, b1.z, b1.w};
#pragma unroll
            for (int m = 0; m < 8; m++)
#pragma unroll
                for (int n = 0; n < 8; n++) acc[m][n] = fmaf(av[m], bv[n], acc[m][n]);
        }
        if (t + 1 < NT) {
            storeS(cur ^ 1);     // write the other buffer (nobody reads it yet)
            __syncthreads();     // single barrier per tile
        }
    }

#pragma unroll
    for (int m = 0; m < 8; m++) {
        int row = rowBase + ty * 8 + m;
        if (row < N_NODES) {
            float4 o0 = make_float4(acc[m][0], acc[m][1], acc[m][2], acc[m][3]);
            float4 o1 = make_float4(acc[m][4], acc[m][5], acc[m][6], acc[m][7]);
            *reinterpret_cast<float4*>(&g_hs[(size_t)row * HIDDEN + tx * 8])     = o0;
            *reinterpret_cast<float4*>(&g_hs[(size_t)row * HIDDEN + tx * 8 + 4]) = o1;
        }
    }
}

// ---------------- Agg1: a1 = relu(dis[w]*(h[w]*dis[w] + sum h[s]*dis[s]) + b1) ----------------
__global__ __launch_bounds__(256) void k_agg1(const float* __restrict__ b1) {
    int w = (blockIdx.x * blockDim.x + threadIdx.x) >> 5;
    if (w >= N_NODES) return;
    int lane = threadIdx.x & 31;
    const float4* hs4 = reinterpret_cast<const float4*>(g_hs);

    float dw = g_dis[w];
    float4 self = hs4[(size_t)w * 32 + lane];
    float4 acc0, acc1, acc2, acc3;
    acc0.x = self.x * dw; acc0.y = self.y * dw; acc0.z = self.z * dw; acc0.w = self.w * dw;
    acc1 = make_float4(0.f, 0.f, 0.f, 0.f);
    acc2 = make_float4(0.f, 0.f, 0.f, 0.f);
    acc3 = make_float4(0.f, 0.f, 0.f, 0.f);

    int i = g_row_ptr[w];
    int e = g_row_ptr[w + 1];
    for (; i + 3 < e; i += 4) {
        int s0 = g_col[i], s1 = g_col[i + 1], s2 = g_col[i + 2], s3 = g_col[i + 3];
        float d0 = g_dis[s0], d1 = g_dis[s1], d2 = g_dis[s2], d3 = g_dis[s3];
        float4 v0 = hs4[(size_t)s0 * 32 + lane];
        float4 v1 = hs4[(size_t)s1 * 32 + lane];
        float4 v2 = hs4[(size_t)s2 * 32 + lane];
        float4 v3 = hs4[(size_t)s3 * 32 + lane];
        acc0.x = fmaf(v0.x, d0, acc0.x); acc0.y = fmaf(v0.y, d0, acc0.y);
        acc0.z = fmaf(v0.z, d0, acc0.z); acc0.w = fmaf(v0.w, d0, acc0.w);
        acc1.x = fmaf(v1.x, d1, acc1.x); acc1.y = fmaf(v1.y, d1, acc1.y);
        acc1.z = fmaf(v1.z, d1, acc1.z); acc1.w = fmaf(v1.w, d1, acc1.w);
        acc2.x = fmaf(v2.x, d2, acc2.x); acc2.y = fmaf(v2.y, d2, acc2.y);
        acc2.z = fmaf(v2.z, d2, acc2.z); acc2.w = fmaf(v2.w, d2, acc2.w);
        acc3.x = fmaf(v3.x, d3, acc3.x); acc3.y = fmaf(v3.y, d3, acc3.y);
        acc3.z = fmaf(v3.z, d3, acc3.z); acc3.w = fmaf(v3.w, d3, acc3.w);
    }
    for (; i < e; i++) {
        int s0 = g_col[i];
        float d0 = g_dis[s0];
        float4 v0 = hs4[(size_t)s0 * 32 + lane];
        acc0.x = fmaf(v0.x, d0, acc0.x); acc0.y = fmaf(v0.y, d0, acc0.y);
        acc0.z = fmaf(v0.z, d0, acc0.z); acc0.w = fmaf(v0.w, d0, acc0.w);
    }
    acc0.x += acc1.x + acc2.x + acc3.x;
    acc0.y += acc1.y + acc2.y + acc3.y;
    acc0.z += acc1.z + acc2.z + acc3.z;
    acc0.w += acc1.w + acc2.w + acc3.w;

    float4 b = reinterpret_cast<const float4*>(b1)[lane];
    float4 r;
    r.x = fmaxf(fmaf(dw, acc0.x, b.x), 0.f);
    r.y = fmaxf(fmaf(dw, acc0.y, b.y), 0.f);
    r.z = fmaxf(fmaf(dw, acc0.z, b.z), 0.f);
    r.w = fmaxf(fmaf(dw, acc0.w, b.w), 0.f);
    reinterpret_cast<float4*>(g_a1)[(size_t)w * 32 + lane] = r;
}

// ---------------- GEMM2: hs2 = (a1 @ W2) * dis[row]   [50000x128]x[128x16] ----------------
__global__ __launch_bounds__(256) void k_gemm2(const float* __restrict__ W2) {
    __shared__ float Ws[HIDDEN * N_CLASSES];
    int tid = threadIdx.x;
    for (int i = tid; i < HIDDEN * N_CLASSES; i += 256) Ws[i] = W2[i];
    __syncthreads();
    int idx = blockIdx.x * 256 + tid;
    if (idx >= N_NODES * N_CLASSES) return;
    int n = idx >> 4;
    int c = idx & 15;
    const float* row = &g_a1[(size_t)n * HIDDEN];
    float acc = 0.f;
#pragma unroll
    for (int k = 0; k < HIDDEN; k++) acc = fmaf(row[k], Ws[k * N_CLASSES + c], acc);
    g_hs2[idx] = acc * g_dis[n];
}

// ---------------- Agg2 + bias + softmax ----------------
__global__ __launch_bounds__(256) void k_agg2(const float* __restrict__ b2,
                                              float* __restrict__ out) {
    int w = (blockIdx.x * blockDim.x + threadIdx.x) >> 5;
    int lane = threadIdx.x & 31;
    int n = w * 2 + (lane >> 4);
    int c = lane & 15;
    if (n >= N_NODES) return;

    float acc0 = g_hs2[(size_t)n * N_CLASSES + c];  // self term
    float acc1 = 0.f, acc2 = 0.f, acc3 = 0.f;
    int i = g_row_ptr[n];
    int e = g_row_ptr[n + 1];
    for (; i + 3 < e; i += 4) {
        int s0 = g_col[i], s1 = g_col[i + 1], s2 = g_col[i + 2], s3 = g_col[i + 3];
        acc0 += g_hs2[(size_t)s0 * N_CLASSES + c];
        acc1 += g_hs2[(size_t)s1 * N_CLASSES + c];
        acc2 += g_hs2[(size_t)s2 * N_CLASSES + c];
        acc3 += g_hs2[(size_t)s3 * N_CLASSES + c];
    }
    for (; i < e; i++) acc0 += g_hs2[(size_t)g_col[i] * N_CLASSES + c];
    acc0 += acc1 + acc2 + acc3;

    float logit = fmaf(g_dis[n], acc0, b2[c]);
    out[(size_t)n * N_CLASSES + c] = logit;

    float m = logit;
#pragma unroll
    for (int o = 8; o > 0; o >>= 1) m = fmaxf(m, __shfl_xor_sync(0xffffffffu, m, o, 16));
    float ex = expf(logit - m);
    float sum = ex;
#pragma unroll
    for (int o = 8; o > 0; o >>= 1) sum += __shfl_xor_sync(0xffffffffu, sum, o, 16);
    out[(size_t)N_NODES * N_CLASSES + (size_t)n * N_CLASSES + c] = ex / sum;
}

// ---------------- launch ----------------
extern "C" void kernel_launch(void* const* d_in, const int* in_sizes, int n_in,
                              void* d_out, int out_size) {
    const float* X  = (const float*)d_in[0];
    const void*  EI = d_in[1];
    const float* W1 = (const float*)d_in[2];
    const float* B1 = (const float*)d_in[3];
    const float* W2 = (const float*)d_in[4];
    const float* B2 = (const float*)d_in[5];
    float* out = (float*)d_out;

    k_init<<<(N_NODES + 255) / 256, 256>>>((const int*)EI);           // 0
    k_count<<<(N_EDGES + 255) / 256, 256>>>(EI);                       // 1
    k_blocksum<<<N_SCAN_BLOCKS, SCAN_CHUNK>>>();                       // 2
    k_gemm1<<<(N_NODES + BM - 1) / BM, 256>>>(X, W1);                  // 3 (profiled)
    k_scan_bs<<<1, 256>>>();                                           // 4
    k_scan_final<<<N_SCAN_BLOCKS, SCAN_CHUNK>>>();                     // 5
    k_scatter<<<(N_EDGES + 255) / 256, 256>>>(EI);                     // 6
    k_agg1<<<(N_NODES * 32 + 255) / 256, 256>>>(B1);                   // 7
    k_gemm2<<<(N_NODES * N_CLASSES + 255) / 256, 256>>>(W2);           // 8
    k_agg2<<<(N_NODES * 16 + 255) / 256, 256>>>(B2, out);              // 9
}

// round 6
// speedup vs baseline: 1.5833x; 1.0387x over previous
#include <cuda_runtime.h>
#include <cuda_bf16.h>
#include <cstdint>

#define N_NODES 50000
#define N_EDGES 1600000
#define IN_FEAT 256
#define HIDDEN  128
#define N_CLASSES 16

#define SCAN_CHUNK 256
#define N_SCAN_BLOCKS ((N_NODES + SCAN_CHUNK - 1) / SCAN_CHUNK)   // 196

// ---------------- scratch (device globals; no allocation allowed) ----------------
__device__ int   g_is64;
__device__ int   g_cnt[N_NODES];
__device__ int   g_row_ptr[N_NODES + 1];
__device__ int   g_cursor[N_NODES];
__device__ int   g_col[N_EDGES];
__device__ int   g_block_sums[N_SCAN_BLOCKS];
__device__ int   g_block_off[N_SCAN_BLOCKS];
__device__ float g_dis[N_NODES];
__device__ __align__(16) float g_hs[N_NODES * HIDDEN];     // X@W1 (unscaled)
__device__ __align__(16) float g_a1[N_NODES * HIDDEN];     // relu(agg1 + b1)
__device__ __align__(16) float g_hs2[N_NODES * N_CLASSES]; // (a1@W2) * dis[row]

// ---------------- init: zero counts + edge dtype probe ----------------
__global__ void k_init(const int* __restrict__ ei) {
    int i = blockIdx.x * blockDim.x + threadIdx.x;
    if (i < N_NODES) g_cnt[i] = 0;
    if (i == 0) {
        int is64 = 1;
        for (int j = 1; j < 256; j += 2)
            if (ei[j] != 0) { is64 = 0; break; }
        g_is64 = is64;
    }
}

__device__ __forceinline__ int load_idx(const void* ei, long long pos) {
    if (g_is64) return (int)((const long long*)ei)[pos];
    return ((const int*)ei)[pos];
}

// ---------------- CSR build ----------------
__global__ void k_count(const void* __restrict__ ei) {
    int e = blockIdx.x * blockDim.x + threadIdx.x;
    if (e < N_EDGES) {
        int d = load_idx(ei, (long long)N_EDGES + e);
        if ((unsigned)d < N_NODES) atomicAdd(&g_cnt[d], 1);
    }
}

__global__ __launch_bounds__(SCAN_CHUNK) void k_blocksum() {
    __shared__ int red[SCAN_CHUNK / 32];
    int idx = blockIdx.x * SCAN_CHUNK + threadIdx.x;
    int v = (idx < N_NODES) ? g_cnt[idx] : 0;
#pragma unroll
    for (int o = 16; o > 0; o >>= 1) v += __shfl_down_sync(0xffffffffu, v, o);
    int lane = threadIdx.x & 31, w = threadIdx.x >> 5;
    if (lane == 0) red[w] = v;
    __syncthreads();
    if (threadIdx.x == 0) {
        int s = 0;
#pragma unroll
        for (int i = 0; i < SCAN_CHUNK / 32; i++) s += red[i];
        g_block_sums[blockIdx.x] = s;
    }
}

__global__ __launch_bounds__(256) void k_scan_bs() {
    __shared__ int s[256];
    int t = threadIdx.x;
    s[t] = (t < N_SCAN_BLOCKS) ? g_block_sums[t] : 0;
    __syncthreads();
#pragma unroll
    for (int off = 1; off < 256; off <<= 1) {
        int v = (t >= off) ? s[t - off] : 0;
        __syncthreads();
        s[t] += v;
        __syncthreads();
    }
    if (t < N_SCAN_BLOCKS) g_block_off[t] = s[t];
    if (t == 255) g_row_ptr[N_NODES] = s[255];
}

__global__ __launch_bounds__(SCAN_CHUNK) void k_scan_final() {
    __shared__ int s[SCAN_CHUNK];
    int t = threadIdx.x;
    int idx = blockIdx.x * SCAN_CHUNK + t;
    int c = (idx < N_NODES) ? g_cnt[idx] : 0;
    s[t] = c;
    __syncthreads();
#pragma unroll
    for (int off = 1; off < SCAN_CHUNK; off <<= 1) {
        int v = (t >= off) ? s[t - off] : 0;
        __syncthreads();
        s[t] += v;
        __syncthreads();
    }
    int blockBase = (blockIdx.x == 0) ? 0 : g_block_off[blockIdx.x - 1];
    if (idx < N_NODES) {
        int excl = blockBase + s[t] - c;
        g_row_ptr[idx] = excl;
        g_cursor[idx]  = excl;
        g_dis[idx] = rsqrtf((float)(c + 1));
    }
}

__global__ void k_scatter(const void* __restrict__ ei) {
    int e = blockIdx.x * blockDim.x + threadIdx.x;
    if (e < N_EDGES) {
        int s = load_idx(ei, e);
        int d = load_idx(ei, (long long)N_EDGES + e);
        if ((unsigned)d < N_NODES && (unsigned)s < N_NODES) {
            int p = atomicAdd(&g_cursor[d], 1);
            g_col[p] = s;
        }
    }
}

// ---------------- GEMM1 (tensor core, tf32x3): g_hs = X @ W1 ----------------
// CTA tile 128x128, K staged 16 at a time. 8 warps in 4(M) x 2(N) grid,
// warp tile 32x64 via mma.m16n8k8 (2 M-tiles x 8 N-tiles).
// Accuracy: x = hi + lo (tf32 split); acc += hi*hi + hi*lo + lo*hi  (fp32 acc).
#define BM 128
#define BK 16

__device__ __forceinline__ uint32_t f2tf32(float x) {
    uint32_t u;
    asm("cvt.rna.tf32.f32 %0, %1;" : "=r"(u) : "f"(x));
    return u;
}

__device__ __forceinline__ void mma_tf32(float* c, const uint32_t* a, uint32_t b0, uint32_t b1) {
    asm volatile(
        "mma.sync.aligned.m16n8k8.row.col.f32.tf32.tf32.f32 "
        "{%0,%1,%2,%3}, {%4,%5,%6,%7}, {%8,%9}, {%0,%1,%2,%3};"
        : "+f"(c[0]), "+f"(c[1]), "+f"(c[2]), "+f"(c[3])
        : "r"(a[0]), "r"(a[1]), "r"(a[2]), "r"(a[3]), "r"(b0), "r"(b1));
}

#define AS_STRIDE 20   // 16 k + pad (conflict-free frag reads)
#define BS_STRIDE 136  // 128 n + 8 pad (conflict-free frag reads)

__global__ __launch_bounds__(256) void k_gemm1(const float* __restrict__ X,
                                               const float* __restrict__ W) {
    __shared__ float As[2][BM][AS_STRIDE];   // [hi/lo][m][k]
    __shared__ float Bs[2][BK][BS_STRIDE];   // [hi/lo][k][n]

    const int tid = threadIdx.x;
    const int lane = tid & 31;
    const int wid = tid >> 5;
    const int rowBase = blockIdx.x * BM;

    // warp grid: 4 (M) x 2 (N)
    const int wm = (wid & 3) * 32;
    const int wn = (wid >> 2) * 64;

    // fragment lane decomposition
    const int grp = lane >> 2;   // 0..7
    const int tig = lane & 3;    // 0..3

    // global A loads: 512 float4 over tile (128 rows x 4 f4)
    const int ar0 = tid >> 2,         ac0 = (tid & 3) * 4;
    const int ar1 = (tid + 256) >> 2, ac1 = ((tid + 256) & 3) * 4;
    const bool aok0 = (rowBase + ar0) < N_NODES;
    const bool aok1 = (rowBase + ar1) < N_NODES;
    // global B loads: 512 float4 over tile (16 rows x 32 f4)
    const int br0 = tid >> 5,         bn0 = (tid & 31) * 4;
    const int br1 = (tid + 256) >> 5, bn1 = ((tid + 256) & 31) * 4;

    float acc[2][8][4];
#pragma unroll
    for (int mt = 0; mt < 2; mt++)
#pragma unroll
        for (int nt = 0; nt < 8; nt++)
#pragma unroll
            for (int j = 0; j < 4; j++) acc[mt][nt][j] = 0.f;

    const int NSTAGE = IN_FEAT / BK;  // 16
#pragma unroll 1
    for (int s = 0; s < NSTAGE; s++) {
        const int k0 = s * BK;
        // ---- global loads ----
        float4 a0 = make_float4(0.f, 0.f, 0.f, 0.f);
        float4 a1 = make_float4(0.f, 0.f, 0.f, 0.f);
        if (aok0) a0 = *reinterpret_cast<const float4*>(&X[(size_t)(rowBase + ar0) * IN_FEAT + k0 + ac0]);
        if (aok1) a1 = *reinterpret_cast<const float4*>(&X[(size_t)(rowBase + ar1) * IN_FEAT + k0 + ac1]);
        float4 b0 = *reinterpret_cast<const float4*>(&W[(size_t)(k0 + br0) * HIDDEN + bn0]);
        float4 b1 = *reinterpret_cast<const float4*>(&W[(size_t)(k0 + br1) * HIDDEN + bn1]);

        __syncthreads();  // previous stage's compute done

        // ---- split + store smem ----
        {
            float va[8] = {a0.x, a0.y, a0.z, a0.w, a1.x, a1.y, a1.z, a1.w};
            float hi[8], lo[8];
#pragma unroll
            for (int j = 0; j < 8; j++) {
                uint32_t h = f2tf32(va[j]);
                hi[j] = __uint_as_float(h);
                lo[j] = __uint_as_float(f2tf32(va[j] - hi[j]));
            }
            *reinterpret_cast<float4*>(&As[0][ar0][ac0]) = make_float4(hi[0], hi[1], hi[2], hi[3]);
            *reinterpret_cast<float4*>(&As[1][ar0][ac0]) = make_float4(lo[0], lo[1], lo[2], lo[3]);
            *reinterpret_cast<float4*>(&As[0][ar1][ac1]) = make_float4(hi[4], hi[5], hi[6], hi[7]);
            *reinterpret_cast<float4*>(&As[1][ar1][ac1]) = make_float4(lo[4], lo[5], lo[6], lo[7]);
        }
        {
            float vb[8] = {b0.x, b0.y, b0.z, b0.w, b1.x, b1.y, b1.z, b1.w};
            float hi[8], lo[8];
#pragma unroll
            for (int j = 0; j < 8; j++) {
                uint32_t h = f2tf32(vb[j]);
                hi[j] = __uint_as_float(h);
                lo[j] = __uint_as_float(f2tf32(vb[j] - hi[j]));
            }
            *reinterpret_cast<float4*>(&Bs[0][br0][bn0]) = make_float4(hi[0], hi[1], hi[2], hi[3]);
            *reinterpret_cast<float4*>(&Bs[1][br0][bn0]) = make_float4(lo[0], lo[1], lo[2], lo[3]);
            *reinterpret_cast<float4*>(&Bs[0][br1][bn1]) = make_float4(hi[4], hi[5], hi[6], hi[7]);
            *reinterpret_cast<float4*>(&Bs[1][br1][bn1]) = make_float4(lo[4], lo[5], lo[6], lo[7]);
        }
        __syncthreads();

        // ---- compute: 2 k8 steps ----
#pragma unroll
        for (int ks = 0; ks < BK; ks += 8) {
            uint32_t ah[2][4], al[2][4];
#pragma unroll
            for (int mt = 0; mt < 2; mt++) {
                int r = wm + mt * 16 + grp;
                int c = ks + tig;
                ah[mt][0] = __float_as_uint(As[0][r][c]);
                ah[mt][1] = __float_as_uint(As[0][r + 8][c]);
                ah[mt][2] = __float_as_uint(As[0][r][c + 4]);
                ah[mt][3] = __float_as_uint(As[0][r + 8][c + 4]);
                al[mt][0] = __float_as_uint(As[1][r][c]);
                al[mt][1] = __float_as_uint(As[1][r + 8][c]);
                al[mt][2] = __float_as_uint(As[1][r][c + 4]);
                al[mt][3] = __float_as_uint(As[1][r + 8][c + 4]);
            }
#pragma unroll
            for (int nt = 0; nt < 8; nt++) {
                int n = wn + nt * 8 + grp;
                int c = ks + tig;
                uint32_t bh0 = __float_as_uint(Bs[0][c][n]);
                uint32_t bh1 = __float_as_uint(Bs[0][c + 4][n]);
                uint32_t bl0 = __float_as_uint(Bs[1][c][n]);
                uint32_t bl1 = __float_as_uint(Bs[1][c + 4][n]);
#pragma unroll
                for (int mt = 0; mt < 2; mt++) {
                    mma_tf32(acc[mt][nt], ah[mt], bh0, bh1);   // hi*hi
                    mma_tf32(acc[mt][nt], ah[mt], bl0, bl1);   // hi*lo
                    mma_tf32(acc[mt][nt], al[mt], bh0, bh1);   // lo*hi
                }
            }
        }
    }

    // ---- epilogue: write g_hs ----
#pragma unroll
    for (int mt = 0; mt < 2; mt++) {
#pragma unroll
        for (int nt = 0; nt < 8; nt++) {
            int row0 = rowBase + wm + mt * 16 + grp;
            int col  = wn + nt * 8 + tig * 2;
            if (row0 < N_NODES)
                *reinterpret_cast<float2*>(&g_hs[(size_t)row0 * HIDDEN + col]) =
                    make_float2(acc[mt][nt][0], acc[mt][nt][1]);
            int row1 = row0 + 8;
            if (row1 < N_NODES)
                *reinterpret_cast<float2*>(&g_hs[(size_t)row1 * HIDDEN + col]) =
                    make_float2(acc[mt][nt][2], acc[mt][nt][3]);
        }
    }
}

// ---------------- Agg1: a1 = relu(dis[w]*(h[w]*dis[w] + sum h[s]*dis[s]) + b1) ----------------
__global__ __launch_bounds__(256) void k_agg1(const float* __restrict__ b1) {
    int w = (blockIdx.x * blockDim.x + threadIdx.x) >> 5;
    if (w >= N_NODES) return;
    int lane = threadIdx.x & 31;
    const float4* hs4 = reinterpret_cast<const float4*>(g_hs);

    float dw = g_dis[w];
    float4 self = hs4[(size_t)w * 32 + lane];
    float4 acc0, acc1, acc2, acc3;
    acc0.x = self.x * dw; acc0.y = self.y * dw; acc0.z = self.z * dw; acc0.w = self.w * dw;
    acc1 = make_float4(0.f, 0.f, 0.f, 0.f);
    acc2 = make_float4(0.f, 0.f, 0.f, 0.f);
    acc3 = make_float4(0.f, 0.f, 0.f, 0.f);

    int i = g_row_ptr[w];
    int e = g_row_ptr[w + 1];
    for (; i + 3 < e; i += 4) {
        int s0 = g_col[i], s1 = g_col[i + 1], s2 = g_col[i + 2], s3 = g_col[i + 3];
        float d0 = g_dis[s0], d1 = g_dis[s1], d2 = g_dis[s2], d3 = g_dis[s3];
        float4 v0 = hs4[(size_t)s0 * 32 + lane];
        float4 v1 = hs4[(size_t)s1 * 32 + lane];
        float4 v2 = hs4[(size_t)s2 * 32 + lane];
        float4 v3 = hs4[(size_t)s3 * 32 + lane];
        acc0.x = fmaf(v0.x, d0, acc0.x); acc0.y = fmaf(v0.y, d0, acc0.y);
        acc0.z = fmaf(v0.z, d0, acc0.z); acc0.w = fmaf(v0.w, d0, acc0.w);
        acc1.x = fmaf(v1.x, d1, acc1.x); acc1.y = fmaf(v1.y, d1, acc1.y);
        acc1.z = fmaf(v1.z, d1, acc1.z); acc1.w = fmaf(v1.w, d1, acc1.w);
        acc2.x = fmaf(v2.x, d2, acc2.x); acc2.y = fmaf(v2.y, d2, acc2.y);
        acc2.z = fmaf(v2.z, d2, acc2.z); acc2.w = fmaf(v2.w, d2, acc2.w);
        acc3.x = fmaf(v3.x, d3, acc3.x); acc3.y = fmaf(v3.y, d3, acc3.y);
        acc3.z = fmaf(v3.z, d3, acc3.z); acc3.w = fmaf(v3.w, d3, acc3.w);
    }
    for (; i < e; i++) {
        int s0 = g_col[i];
        float d0 = g_dis[s0];
        float4 v0 = hs4[(size_t)s0 * 32 + lane];
        acc0.x = fmaf(v0.x, d0, acc0.x); acc0.y = fmaf(v0.y, d0, acc0.y);
        acc0.z = fmaf(v0.z, d0, acc0.z); acc0.w = fmaf(v0.w, d0, acc0.w);
    }
    acc0.x += acc1.x + acc2.x + acc3.x;
    acc0.y += acc1.y + acc2.y + acc3.y;
    acc0.z += acc1.z + acc2.z + acc3.z;
    acc0.w += acc1.w + acc2.w + acc3.w;

    float4 b = reinterpret_cast<const float4*>(b1)[lane];
    float4 r;
    r.x = fmaxf(fmaf(dw, acc0.x, b.x), 0.f);
    r.y = fmaxf(fmaf(dw, acc0.y, b.y), 0.f);
    r.z = fmaxf(fmaf(dw, acc0.z, b.z), 0.f);
    r.w = fmaxf(fmaf(dw, acc0.w, b.w), 0.f);
    reinterpret_cast<float4*>(g_a1)[(size_t)w * 32 + lane] = r;
}

// ---------------- GEMM2: hs2 = (a1 @ W2) * dis[row]   [50000x128]x[128x16] ----------------
__global__ __launch_bounds__(256) void k_gemm2(const float* __restrict__ W2) {
    __shared__ float Ws[HIDDEN * N_CLASSES];
    int tid = threadIdx.x;
    for (int i = tid; i < HIDDEN * N_CLASSES; i += 256) Ws[i] = W2[i];
    __syncthreads();
    int idx = blockIdx.x * 256 + tid;
    if (idx >= N_NODES * N_CLASSES) return;
    int n = idx >> 4;
    int c = idx & 15;
    const float* row = &g_a1[(size_t)n * HIDDEN];
    float acc = 0.f;
#pragma unroll
    for (int k = 0; k < HIDDEN; k++) acc = fmaf(row[k], Ws[k * N_CLASSES + c], acc);
    g_hs2[idx] = acc * g_dis[n];
}

// ---------------- Agg2 + bias + softmax ----------------
__global__ __launch_bounds__(256) void k_agg2(const float* __restrict__ b2,
                                              float* __restrict__ out) {
    int w = (blockIdx.x * blockDim.x + threadIdx.x) >> 5;
    int lane = threadIdx.x & 31;
    int n = w * 2 + (lane >> 4);
    int c = lane & 15;
    if (n >= N_NODES) return;

    float acc0 = g_hs2[(size_t)n * N_CLASSES + c];  // self term
    float acc1 = 0.f, acc2 = 0.f, acc3 = 0.f;
    int i = g_row_ptr[n];
    int e = g_row_ptr[n + 1];
    for (; i + 3 < e; i += 4) {
        int s0 = g_col[i], s1 = g_col[i + 1], s2 = g_col[i + 2], s3 = g_col[i + 3];
        acc0 += g_hs2[(size_t)s0 * N_CLASSES + c];
        acc1 += g_hs2[(size_t)s1 * N_CLASSES + c];
        acc2 += g_hs2[(size_t)s2 * N_CLASSES + c];
        acc3 += g_hs2[(size_t)s3 * N_CLASSES + c];
    }
    for (; i < e; i++) acc0 += g_hs2[(size_t)g_col[i] * N_CLASSES + c];
    acc0 += acc1 + acc2 + acc3;

    float logit = fmaf(g_dis[n], acc0, b2[c]);
    out[(size_t)n * N_CLASSES + c] = logit;

    float m = logit;
#pragma unroll
    for (int o = 8; o > 0; o >>= 1) m = fmaxf(m, __shfl_xor_sync(0xffffffffu, m, o, 16));
    float ex = expf(logit - m);
    float sum = ex;
#pragma unroll
    for (int o = 8; o > 0; o >>= 1) sum += __shfl_xor_sync(0xffffffffu, sum, o, 16);
    out[(size_t)N_NODES * N_CLASSES + (size_t)n * N_CLASSES + c] = ex / sum;
}

// ---------------- launch ----------------
extern "C" void kernel_launch(void* const* d_in, const int* in_sizes, int n_in,
                              void* d_out, int out_size) {
    const float* X  = (const float*)d_in[0];
    const void*  EI = d_in[1];
    const float* W1 = (const float*)d_in[2];
    const float* B1 = (const float*)d_in[3];
    const float* W2 = (const float*)d_in[4];
    const float* B2 = (const float*)d_in[5];
    float* out = (float*)d_out;

    k_init<<<(N_NODES + 255) / 256, 256>>>((const int*)EI);           // 0
    k_count<<<(N_EDGES + 255) / 256, 256>>>(EI);                       // 1
    k_blocksum<<<N_SCAN_BLOCKS, SCAN_CHUNK>>>();                       // 2
    k_gemm1<<<(N_NODES + BM - 1) / BM, 256>>>(X, W1);                  // 3 (profiled)
    k_scan_bs<<<1, 256>>>();                                           // 4
    k_scan_final<<<N_SCAN_BLOCKS, SCAN_CHUNK>>>();                     // 5
    k_scatter<<<(N_EDGES + 255) / 256, 256>>>(EI);                     // 6
    k_agg1<<<(N_NODES * 32 + 255) / 256, 256>>>(B1);                   // 7
    k_gemm2<<<(N_NODES * N_CLASSES + 255) / 256, 256>>>(W2);           // 8
    k_agg2<<<(N_NODES * 16 + 255) / 256, 256>>>(B2, out);              // 9
}